// round 9
// baseline (speedup 1.0000x reference)
#include <cuda_runtime.h>
#include <cstdint>

#define N_NODES 100000
#define N_EDGES 300000
#define HID 32

// Scratch (device globals; no allocation allowed). 16B-aligned for v4 access.
__device__ __align__(16) float g_agg1[N_NODES * HID];  // layer1 edge-sum accumulator (memset 0)
__device__ __align__(16) float g_uvw[N_NODES * 96];    // per-node rows: [u(32) | v(32) | w(32)]
__device__ __align__(16) float g_agg2[N_NODES * HID];  // layer2 accumulator

__device__ __forceinline__ void red_add_v4(float* addr, float a, float b, float c, float d) {
    asm volatile("red.global.add.v4.f32 [%0], {%1,%2,%3,%4};"
                 :: "l"(addr), "f"(a), "f"(b), "f"(c), "f"(d) : "memory");
}

__device__ __forceinline__ uint32_t to_tf32(float f) {
    uint32_t r; asm("cvt.rna.tf32.f32 %0, %1;" : "=r"(r) : "f"(f)); return r;
}

__device__ __forceinline__ void mma_tf32_16n8k8(float c[4],
                                                uint32_t a0, uint32_t a1, uint32_t a2, uint32_t a3,
                                                uint32_t b0, uint32_t b1) {
    asm volatile(
        "mma.sync.aligned.m16n8k8.row.col.f32.tf32.tf32.f32 "
        "{%0,%1,%2,%3}, {%4,%5,%6,%7}, {%8,%9}, {%0,%1,%2,%3};"
        : "+f"(c[0]), "+f"(c[1]), "+f"(c[2]), "+f"(c[3])
        : "r"(a0), "r"(a1), "r"(a2), "r"(a3), "r"(b0), "r"(b1));
}

// ---------------------------------------------------------------------------
// K2: layer-1 edge messages. 2 edges per thread (even/odd pair), 4 channels.
// ---------------------------------------------------------------------------
__global__ void k2_edges1(const int* __restrict__ ei,
                          const float* __restrict__ ea,
                          const float* __restrict__ nn1_w,
                          const float* __restrict__ nn1_b,
                          const float* __restrict__ x) {
    int t = blockIdx.x * blockDim.x + threadIdx.x;
    if (t >= N_EDGES * 4) return;
    int e = (t >> 3) * 2;
    int q = (t & 7) * 4;
    int2   ss  = *reinterpret_cast<const int2*>(&ei[e]);
    int2   dd  = *reinterpret_cast<const int2*>(&ei[N_EDGES + e]);
    float4 eav = *reinterpret_cast<const float4*>(&ea[2 * e]);
    float2 xa  = *reinterpret_cast<const float2*>(&x[ss.x * 2]);
    float2 xb  = *reinterpret_cast<const float2*>(&x[ss.y * 2]);

    float m0[4], m1[4];
#pragma unroll
    for (int c = 0; c < 4; c++) {
        int ch = q + c, ch2 = ch + HID;
        float wA0 = nn1_w[2 * ch + 0],  wA1 = nn1_w[2 * ch + 1],  bA = nn1_b[ch];
        float wB0 = nn1_w[2 * ch2 + 0], wB1 = nn1_w[2 * ch2 + 1], bB = nn1_b[ch2];
        float w0a = fmaf(wA0, eav.x, fmaf(wA1, eav.y, bA));
        float w1a = fmaf(wB0, eav.x, fmaf(wB1, eav.y, bB));
        m0[c] = fmaf(xa.x, w0a, xa.y * w1a);
        float w0b = fmaf(wA0, eav.z, fmaf(wA1, eav.w, bA));
        float w1b = fmaf(wB0, eav.z, fmaf(wB1, eav.w, bB));
        m1[c] = fmaf(xb.x, w0b, xb.y * w1b);
    }
    red_add_v4(&g_agg1[dd.x * HID + q], m0[0], m0[1], m0[2], m0[3]);
    red_add_v4(&g_agg1[dd.y * HID + q], m1[0], m1[1], m1[2], m1[3]);
}

// ---------------------------------------------------------------------------
// K3: tensor-core per-node precompute, 3-term split-tf32 (~fp32 accuracy):
//   D = Hhi@Whi + Hhi@Wlo + Hlo@Whi,  lo = tf32(val - float(hi))
// Dynamic smem (70KB): sHhi/sHlo [128*36], sWhi/sWlo [32*136].
// 8 warps x 16-node m-tiles; 16 n-tiles x 4 k-chunks x 3 terms.
// ---------------------------------------------------------------------------
#define K3_DYN_BYTES ((2 * 128 * 36 + 2 * 32 * 136) * 4)
__global__ void k3_node2(const float* __restrict__ x,
                         const float* __restrict__ root1,
                         const float* __restrict__ bias1,
                         const float* __restrict__ nn2_w,
                         const float* __restrict__ nn2_b,
                         const float* __restrict__ root2,
                         const float* __restrict__ bias2) {
    extern __shared__ uint32_t dyn[];
    uint32_t* sHhi = dyn;                 // [128*36]
    uint32_t* sHlo = sHhi + 128 * 36;     // [128*36]
    uint32_t* sWhi = sHlo + 128 * 36;     // [32*136]
    uint32_t* sWlo = sWhi + 32 * 136;     // [32*136]
    __shared__ float sB2[32], sR1[64], sB1[32];
    int tid = threadIdx.x;
    if (tid < 64) sR1[tid] = root1[tid];
    if (tid < 32) { sB1[tid] = bias1[tid]; sB2[tid] = bias2[tid]; }
    __syncthreads();

    // Stage Wcat hi/lo
    for (int idx = tid; idx < 32 * 128; idx += 256) {
        int k = idx >> 7, c = idx & 127;
        float w;
        if (c < 32)       w = nn2_w[(k * 32 + c) * 2 + 0];
        else if (c < 64)  w = nn2_w[(k * 32 + c - 32) * 2 + 1];
        else if (c < 96)  w = nn2_b[k * 32 + c - 64];
        else              w = root2[k * 32 + c - 96];
        uint32_t hi = to_tf32(w);
        sWhi[k * 136 + c] = hi;
        sWlo[k * 136 + c] = to_tf32(w - __uint_as_float(hi));
    }

    // Stage H hi/lo
    int blockBase = blockIdx.x * 128;
    for (int idx = tid; idx < 128 * 32; idx += 256) {
        int m = idx >> 5, kk = idx & 31;
        int n = blockBase + m;
        float val = 0.0f;
        if (n < N_NODES) {
            float2 xv = *reinterpret_cast<const float2*>(&x[n * 2]);
            float root = fmaf(xv.x, sR1[kk], fmaf(xv.y, sR1[HID + kk], sB1[kk]));
            val = fmaxf(g_agg1[n * HID + kk] + root, 0.0f);
        }
        uint32_t hi = to_tf32(val);
        sHhi[m * 36 + kk] = hi;
        sHlo[m * 36 + kk] = to_tf32(val - __uint_as_float(hi));
    }
    __syncthreads();

    int warp = tid >> 5, lane = tid & 31;
    int gid = lane >> 2, tig = lane & 3;
    int mloc = warp * 16;

    uint32_t ah[4][4], al[4][4];
#pragma unroll
    for (int kc = 0; kc < 4; kc++) {
        int k0 = kc * 8 + tig;
        int r0 = (mloc + gid) * 36, r1 = (mloc + gid + 8) * 36;
        ah[kc][0] = sHhi[r0 + k0];     ah[kc][1] = sHhi[r1 + k0];
        ah[kc][2] = sHhi[r0 + k0 + 4]; ah[kc][3] = sHhi[r1 + k0 + 4];
        al[kc][0] = sHlo[r0 + k0];     al[kc][1] = sHlo[r1 + k0];
        al[kc][2] = sHlo[r0 + k0 + 4]; al[kc][3] = sHlo[r1 + k0 + 4];
    }

    int node0 = blockBase + mloc + gid;
    int node1 = node0 + 8;
#pragma unroll
    for (int nt = 0; nt < 16; nt++) {
        float c[4] = {0.0f, 0.0f, 0.0f, 0.0f};
#pragma unroll
        for (int kc = 0; kc < 4; kc++) {
            int kr0 = (kc * 8 + tig) * 136 + nt * 8 + gid;
            int kr1 = (kc * 8 + tig + 4) * 136 + nt * 8 + gid;
            uint32_t bh0 = sWhi[kr0], bh1 = sWhi[kr1];
            uint32_t bl0 = sWlo[kr0], bl1 = sWlo[kr1];
            mma_tf32_16n8k8(c, ah[kc][0], ah[kc][1], ah[kc][2], ah[kc][3], bh0, bh1);
            mma_tf32_16n8k8(c, ah[kc][0], ah[kc][1], ah[kc][2], ah[kc][3], bl0, bl1);
            mma_tf32_16n8k8(c, al[kc][0], al[kc][1], al[kc][2], al[kc][3], bh0, bh1);
        }
        int chan = nt * 8 + tig * 2;
        if (nt < 12) {
            if (node0 < N_NODES)
                *reinterpret_cast<float2*>(&g_uvw[node0 * 96 + chan]) = make_float2(c[0], c[1]);
            if (node1 < N_NODES)
                *reinterpret_cast<float2*>(&g_uvw[node1 * 96 + chan]) = make_float2(c[2], c[3]);
        } else {
            int cb = chan - 96;
            float b0f = sB2[cb], b1f = sB2[cb + 1];
            if (node0 < N_NODES)
                *reinterpret_cast<float2*>(&g_agg2[node0 * HID + cb]) = make_float2(c[0] + b0f, c[1] + b1f);
            if (node1 < N_NODES)
                *reinterpret_cast<float2*>(&g_agg2[node1 * HID + cb]) = make_float2(c[2] + b0f, c[3] + b1f);
        }
    }
}

// ---------------------------------------------------------------------------
// K4: layer-2 edge messages. 2 edges per thread, 4 channels (float4) each.
// ---------------------------------------------------------------------------
__global__ void k4_edges2(const int* __restrict__ ei,
                          const float* __restrict__ ea) {
    int t = blockIdx.x * blockDim.x + threadIdx.x;
    if (t >= N_EDGES * 4) return;
    int e = (t >> 3) * 2;
    int q = (t & 7) * 4;
    int2   ss  = *reinterpret_cast<const int2*>(&ei[e]);
    int2   dd  = *reinterpret_cast<const int2*>(&ei[N_EDGES + e]);
    float4 eav = *reinterpret_cast<const float4*>(&ea[2 * e]);

    const float* ba = g_uvw + ss.x * 96;
    const float* bb = g_uvw + ss.y * 96;
    float4 u0 = *reinterpret_cast<const float4*>(ba + q);
    float4 v0 = *reinterpret_cast<const float4*>(ba + 32 + q);
    float4 w0 = *reinterpret_cast<const float4*>(ba + 64 + q);
    float4 u1 = *reinterpret_cast<const float4*>(bb + q);
    float4 v1 = *reinterpret_cast<const float4*>(bb + 32 + q);
    float4 w1 = *reinterpret_cast<const float4*>(bb + 64 + q);

    float a0 = fmaf(eav.x, u0.x, fmaf(eav.y, v0.x, w0.x));
    float a1 = fmaf(eav.x, u0.y, fmaf(eav.y, v0.y, w0.y));
    float a2 = fmaf(eav.x, u0.z, fmaf(eav.y, v0.z, w0.z));
    float a3 = fmaf(eav.x, u0.w, fmaf(eav.y, v0.w, w0.w));
    red_add_v4(&g_agg2[dd.x * HID + q], a0, a1, a2, a3);

    float b0 = fmaf(eav.z, u1.x, fmaf(eav.w, v1.x, w1.x));
    float b1 = fmaf(eav.z, u1.y, fmaf(eav.w, v1.y, w1.y));
    float b2 = fmaf(eav.z, u1.z, fmaf(eav.w, v1.z, w1.z));
    float b3 = fmaf(eav.z, u1.w, fmaf(eav.w, v1.w, w1.w));
    red_add_v4(&g_agg2[dd.y * HID + q], b0, b1, b2, b3);
}

// ---------------------------------------------------------------------------
// K5: tensor-core epilogue, 3-term split-tf32.
//   h2 = relu(agg2); D = h2@fc1_w^T; h3 = relu(D + fc1_b);
//   out = h3 . fc2_w + fc2_b   (fc2 dot folded in, 4-lane shfl reduce)
// 8 warps x 16-node m-tiles (128 nodes/block); 4 n-tiles x 4 kc x 3 terms.
// Static smem 47.4KB (fits 48KB).
// ---------------------------------------------------------------------------
__global__ void k5_final(const float* __restrict__ fc1_w,
                         const float* __restrict__ fc1_b,
                         const float* __restrict__ fc2_w,
                         const float* __restrict__ fc2_b,
                         float* __restrict__ out) {
    __shared__ uint32_t sHhi[128 * 36], sHlo[128 * 36];  // h2 tf32 hi/lo
    __shared__ uint32_t sWhi[32 * 40], sWlo[32 * 40];    // fc1_w^T: sW[i*40+o]
    __shared__ float sb1[32], sf2[32];
    int tid = threadIdx.x;
    if (tid < 32) { sb1[tid] = fc1_b[tid]; sf2[tid] = fc2_w[tid]; }

    // Stage fc1_w transposed (coalesced global read, scattered smem write)
    for (int k = tid; k < 1024; k += 256) {
        int o = k >> 5, i = k & 31;
        float w = fc1_w[k];
        uint32_t hi = to_tf32(w);
        sWhi[i * 40 + o] = hi;
        sWlo[i * 40 + o] = to_tf32(w - __uint_as_float(hi));
    }

    int base = blockIdx.x * 128;
    for (int idx = tid; idx < 128 * 32; idx += 256) {
        int m = idx >> 5, i = idx & 31;
        int n = base + m;
        float v = 0.0f;
        if (n < N_NODES) v = fmaxf(g_agg2[n * HID + i], 0.0f);
        uint32_t hi = to_tf32(v);
        sHhi[m * 36 + i] = hi;
        sHlo[m * 36 + i] = to_tf32(v - __uint_as_float(hi));
    }
    __syncthreads();

    int warp = tid >> 5, lane = tid & 31;
    int gid = lane >> 2, tig = lane & 3;
    int mloc = warp * 16;

    uint32_t ah[4][4], al[4][4];
#pragma unroll
    for (int kc = 0; kc < 4; kc++) {
        int k0 = kc * 8 + tig;
        int r0 = (mloc + gid) * 36, r1 = (mloc + gid + 8) * 36;
        ah[kc][0] = sHhi[r0 + k0];     ah[kc][1] = sHhi[r1 + k0];
        ah[kc][2] = sHhi[r0 + k0 + 4]; ah[kc][3] = sHhi[r1 + k0 + 4];
        al[kc][0] = sHlo[r0 + k0];     al[kc][1] = sHlo[r1 + k0];
        al[kc][2] = sHlo[r0 + k0 + 4]; al[kc][3] = sHlo[r1 + k0 + 4];
    }

    float pt0 = 0.0f, pt1 = 0.0f;   // partial fc2 dots for node0 / node1
#pragma unroll
    for (int nt = 0; nt < 4; nt++) {
        float c[4] = {0.0f, 0.0f, 0.0f, 0.0f};
#pragma unroll
        for (int kc = 0; kc < 4; kc++) {
            int kr0 = (kc * 8 + tig) * 40 + nt * 8 + gid;
            int kr1 = (kc * 8 + tig + 4) * 40 + nt * 8 + gid;
            uint32_t bh0 = sWhi[kr0], bh1 = sWhi[kr1];
            uint32_t bl0 = sWlo[kr0], bl1 = sWlo[kr1];
            mma_tf32_16n8k8(c, ah[kc][0], ah[kc][1], ah[kc][2], ah[kc][3], bh0, bh1);
            mma_tf32_16n8k8(c, ah[kc][0], ah[kc][1], ah[kc][2], ah[kc][3], bl0, bl1);
            mma_tf32_16n8k8(c, al[kc][0], al[kc][1], al[kc][2], al[kc][3], bh0, bh1);
        }
        int chan = nt * 8 + tig * 2;
        float f0 = sf2[chan], f1 = sf2[chan + 1];
        float b0 = sb1[chan], b1 = sb1[chan + 1];
        pt0 = fmaf(fmaxf(c[0] + b0, 0.0f), f0, pt0);
        pt0 = fmaf(fmaxf(c[1] + b1, 0.0f), f1, pt0);
        pt1 = fmaf(fmaxf(c[2] + b0, 0.0f), f0, pt1);
        pt1 = fmaf(fmaxf(c[3] + b1, 0.0f), f1, pt1);
    }
    // Reduce across the 4-lane tig group (lanes 4*gid .. 4*gid+3)
    pt0 += __shfl_xor_sync(0xFFFFFFFFu, pt0, 1);
    pt0 += __shfl_xor_sync(0xFFFFFFFFu, pt0, 2);
    pt1 += __shfl_xor_sync(0xFFFFFFFFu, pt1, 1);
    pt1 += __shfl_xor_sync(0xFFFFFFFFu, pt1, 2);
    if (tig == 0) {
        float bias = fc2_b[0];
        int node0 = base + mloc + gid;
        int node1 = node0 + 8;
        if (node0 < N_NODES) out[node0] = pt0 + bias;
        if (node1 < N_NODES) out[node1] = pt1 + bias;
    }
}

// ---------------------------------------------------------------------------
extern "C" void kernel_launch(void* const* d_in, const int* in_sizes, int n_in,
                              void* d_out, int out_size) {
    const float* x       = (const float*)d_in[0];
    const int*   ei      = (const int*)  d_in[1];
    const float* ea      = (const float*)d_in[2];
    const float* nn1_w   = (const float*)d_in[3];
    const float* nn1_b   = (const float*)d_in[4];
    const float* root1   = (const float*)d_in[5];
    const float* bias1   = (const float*)d_in[6];
    const float* nn2_w   = (const float*)d_in[7];
    const float* nn2_b   = (const float*)d_in[8];
    const float* root2   = (const float*)d_in[9];
    const float* bias2   = (const float*)d_in[10];
    const float* fc1_w   = (const float*)d_in[11];
    const float* fc1_b   = (const float*)d_in[12];
    const float* fc2_w   = (const float*)d_in[13];
    const float* fc2_b   = (const float*)d_in[14];
    float* out = (float*)d_out;

    const int tpb = 256;
    int gridEdge = (N_EDGES * 4 + tpb - 1) / tpb;   // 4688
    int gridK3   = (N_NODES + 127) / 128;           // 782
    int gridK5   = (N_NODES + 127) / 128;           // 782

    // Host-side attribute set (runs at capture time, not in the timed graph).
    cudaFuncSetAttribute(k3_node2, cudaFuncAttributeMaxDynamicSharedMemorySize, K3_DYN_BYTES);

    void* agg1_ptr = nullptr;
    cudaGetSymbolAddress(&agg1_ptr, g_agg1);
    cudaMemsetAsync(agg1_ptr, 0, sizeof(float) * N_NODES * HID, 0);

    k2_edges1<<<gridEdge, tpb>>>(ei, ea, nn1_w, nn1_b, x);
    k3_node2<<<gridK3, tpb, K3_DYN_BYTES>>>(x, root1, bias1, nn2_w, nn2_b, root2, bias2);
    k4_edges2<<<gridEdge, tpb>>>(ei, ea);
    k5_final<<<gridK5, tpb>>>(fc1_w, fc1_b, fc2_w, fc2_b, out);
}

// round 10
// speedup vs baseline: 1.0739x; 1.0739x over previous
#include <cuda_runtime.h>
#include <cstdint>

#define N_NODES 100000
#define N_EDGES 300000
#define HID 32

// Scratch (device globals; no allocation allowed). 16B-aligned for v4 access.
__device__ __align__(16) float g_agg1[N_NODES * HID];  // layer1 edge-sum accumulator (memset 0)
__device__ __align__(16) float g_uvw[N_NODES * 96];    // per-node rows: [u(32) | v(32) | w(32)]
__device__ __align__(16) float g_agg2[N_NODES * HID];  // layer2 accumulator

__device__ __forceinline__ void red_add_v4(float* addr, float a, float b, float c, float d) {
    asm volatile("red.global.add.v4.f32 [%0], {%1,%2,%3,%4};"
                 :: "l"(addr), "f"(a), "f"(b), "f"(c), "f"(d) : "memory");
}

__device__ __forceinline__ uint32_t to_tf32(float f) {
    uint32_t r; asm("cvt.rna.tf32.f32 %0, %1;" : "=r"(r) : "f"(f)); return r;
}

__device__ __forceinline__ void mma_tf32_16n8k8(float c[4],
                                                uint32_t a0, uint32_t a1, uint32_t a2, uint32_t a3,
                                                uint32_t b0, uint32_t b1) {
    asm volatile(
        "mma.sync.aligned.m16n8k8.row.col.f32.tf32.tf32.f32 "
        "{%0,%1,%2,%3}, {%4,%5,%6,%7}, {%8,%9}, {%0,%1,%2,%3};"
        : "+f"(c[0]), "+f"(c[1]), "+f"(c[2]), "+f"(c[3])
        : "r"(a0), "r"(a1), "r"(a2), "r"(a3), "r"(b0), "r"(b1));
}

// ---------------------------------------------------------------------------
// K2: layer-1 edge messages. 2 edges per thread (even/odd pair), 4 channels.
// ---------------------------------------------------------------------------
__global__ void k2_edges1(const int* __restrict__ ei,
                          const float* __restrict__ ea,
                          const float* __restrict__ nn1_w,
                          const float* __restrict__ nn1_b,
                          const float* __restrict__ x) {
    int t = blockIdx.x * blockDim.x + threadIdx.x;
    if (t >= N_EDGES * 4) return;
    int e = (t >> 3) * 2;
    int q = (t & 7) * 4;
    int2   ss  = *reinterpret_cast<const int2*>(&ei[e]);
    int2   dd  = *reinterpret_cast<const int2*>(&ei[N_EDGES + e]);
    float4 eav = *reinterpret_cast<const float4*>(&ea[2 * e]);
    float2 xa  = *reinterpret_cast<const float2*>(&x[ss.x * 2]);
    float2 xb  = *reinterpret_cast<const float2*>(&x[ss.y * 2]);

    float m0[4], m1[4];
#pragma unroll
    for (int c = 0; c < 4; c++) {
        int ch = q + c, ch2 = ch + HID;
        float wA0 = nn1_w[2 * ch + 0],  wA1 = nn1_w[2 * ch + 1],  bA = nn1_b[ch];
        float wB0 = nn1_w[2 * ch2 + 0], wB1 = nn1_w[2 * ch2 + 1], bB = nn1_b[ch2];
        float w0a = fmaf(wA0, eav.x, fmaf(wA1, eav.y, bA));
        float w1a = fmaf(wB0, eav.x, fmaf(wB1, eav.y, bB));
        m0[c] = fmaf(xa.x, w0a, xa.y * w1a);
        float w0b = fmaf(wA0, eav.z, fmaf(wA1, eav.w, bA));
        float w1b = fmaf(wB0, eav.z, fmaf(wB1, eav.w, bB));
        m1[c] = fmaf(xb.x, w0b, xb.y * w1b);
    }
    red_add_v4(&g_agg1[dd.x * HID + q], m0[0], m0[1], m0[2], m0[3]);
    red_add_v4(&g_agg1[dd.y * HID + q], m1[0], m1[1], m1[2], m1[3]);
}

// ---------------------------------------------------------------------------
// K3: tensor-core (tf32 mma.sync) per-node precompute for layer 2 (R8 form).
//   H[128x32] = relu(agg1 + x@root1 + bias1); Wcat[32x128] = [A | B | C | root2]
//   D = H @ Wcat -> chans 0-95 -> g_uvw ; chans 96-127 (+bias2) -> g_agg2
// ---------------------------------------------------------------------------
__global__ void k3_node2(const float* __restrict__ x,
                         const float* __restrict__ root1,
                         const float* __restrict__ bias1,
                         const float* __restrict__ nn2_w,
                         const float* __restrict__ nn2_b,
                         const float* __restrict__ root2,
                         const float* __restrict__ bias2) {
    __shared__ uint32_t sH[128 * 36];   // tf32 H: sH[m*36 + k]
    __shared__ uint32_t sW[32 * 136];   // tf32 Wcat: sW[k*136 + chan]
    __shared__ float sB2[32], sR1[64], sB1[32];
    int tid = threadIdx.x;
    if (tid < 64) sR1[tid] = root1[tid];
    if (tid < 32) { sB1[tid] = bias1[tid]; sB2[tid] = bias2[tid]; }
    __syncthreads();

    for (int idx = tid; idx < 32 * 128; idx += 256) {
        int k = idx >> 7, c = idx & 127;
        float w;
        if (c < 32)       w = nn2_w[(k * 32 + c) * 2 + 0];
        else if (c < 64)  w = nn2_w[(k * 32 + c - 32) * 2 + 1];
        else if (c < 96)  w = nn2_b[k * 32 + c - 64];
        else              w = root2[k * 32 + c - 96];
        sW[k * 136 + c] = to_tf32(w);
    }

    int blockBase = blockIdx.x * 128;
    for (int idx = tid; idx < 128 * 32; idx += 256) {
        int m = idx >> 5, kk = idx & 31;
        int n = blockBase + m;
        float val = 0.0f;
        if (n < N_NODES) {
            float2 xv = *reinterpret_cast<const float2*>(&x[n * 2]);
            float root = fmaf(xv.x, sR1[kk], fmaf(xv.y, sR1[HID + kk], sB1[kk]));
            val = fmaxf(g_agg1[n * HID + kk] + root, 0.0f);
        }
        sH[m * 36 + kk] = to_tf32(val);
    }
    __syncthreads();

    int warp = tid >> 5, lane = tid & 31;
    int gid = lane >> 2, tig = lane & 3;
    int mloc = warp * 16;

    uint32_t a[4][4];
#pragma unroll
    for (int kc = 0; kc < 4; kc++) {
        int k0 = kc * 8 + tig;
        a[kc][0] = sH[(mloc + gid) * 36 + k0];
        a[kc][1] = sH[(mloc + gid + 8) * 36 + k0];
        a[kc][2] = sH[(mloc + gid) * 36 + k0 + 4];
        a[kc][3] = sH[(mloc + gid + 8) * 36 + k0 + 4];
    }

    int node0 = blockBase + mloc + gid;
    int node1 = node0 + 8;
#pragma unroll
    for (int nt = 0; nt < 16; nt++) {
        float c[4] = {0.0f, 0.0f, 0.0f, 0.0f};
#pragma unroll
        for (int kc = 0; kc < 4; kc++) {
            uint32_t b0 = sW[(kc * 8 + tig) * 136 + nt * 8 + gid];
            uint32_t b1 = sW[(kc * 8 + tig + 4) * 136 + nt * 8 + gid];
            mma_tf32_16n8k8(c, a[kc][0], a[kc][1], a[kc][2], a[kc][3], b0, b1);
        }
        int chan = nt * 8 + tig * 2;
        if (nt < 12) {
            if (node0 < N_NODES)
                *reinterpret_cast<float2*>(&g_uvw[node0 * 96 + chan]) = make_float2(c[0], c[1]);
            if (node1 < N_NODES)
                *reinterpret_cast<float2*>(&g_uvw[node1 * 96 + chan]) = make_float2(c[2], c[3]);
        } else {
            int cb = chan - 96;
            float b0f = sB2[cb], b1f = sB2[cb + 1];
            if (node0 < N_NODES)
                *reinterpret_cast<float2*>(&g_agg2[node0 * HID + cb]) = make_float2(c[0] + b0f, c[1] + b1f);
            if (node1 < N_NODES)
                *reinterpret_cast<float2*>(&g_agg2[node1 * HID + cb]) = make_float2(c[2] + b0f, c[3] + b1f);
        }
    }
}

// ---------------------------------------------------------------------------
// K4: layer-2 edge messages. 2 edges per thread, 4 channels (float4) each.
// ---------------------------------------------------------------------------
__global__ void k4_edges2(const int* __restrict__ ei,
                          const float* __restrict__ ea) {
    int t = blockIdx.x * blockDim.x + threadIdx.x;
    if (t >= N_EDGES * 4) return;
    int e = (t >> 3) * 2;
    int q = (t & 7) * 4;
    int2   ss  = *reinterpret_cast<const int2*>(&ei[e]);
    int2   dd  = *reinterpret_cast<const int2*>(&ei[N_EDGES + e]);
    float4 eav = *reinterpret_cast<const float4*>(&ea[2 * e]);

    const float* ba = g_uvw + ss.x * 96;
    const float* bb = g_uvw + ss.y * 96;
    float4 u0 = *reinterpret_cast<const float4*>(ba + q);
    float4 v0 = *reinterpret_cast<const float4*>(ba + 32 + q);
    float4 w0 = *reinterpret_cast<const float4*>(ba + 64 + q);
    float4 u1 = *reinterpret_cast<const float4*>(bb + q);
    float4 v1 = *reinterpret_cast<const float4*>(bb + 32 + q);
    float4 w1 = *reinterpret_cast<const float4*>(bb + 64 + q);

    float a0 = fmaf(eav.x, u0.x, fmaf(eav.y, v0.x, w0.x));
    float a1 = fmaf(eav.x, u0.y, fmaf(eav.y, v0.y, w0.y));
    float a2 = fmaf(eav.x, u0.z, fmaf(eav.y, v0.z, w0.z));
    float a3 = fmaf(eav.x, u0.w, fmaf(eav.y, v0.w, w0.w));
    red_add_v4(&g_agg2[dd.x * HID + q], a0, a1, a2, a3);

    float b0 = fmaf(eav.z, u1.x, fmaf(eav.w, v1.x, w1.x));
    float b1 = fmaf(eav.z, u1.y, fmaf(eav.w, v1.y, w1.y));
    float b2 = fmaf(eav.z, u1.z, fmaf(eav.w, v1.z, w1.z));
    float b3 = fmaf(eav.z, u1.w, fmaf(eav.w, v1.w, w1.w));
    red_add_v4(&g_agg2[dd.y * HID + q], b0, b1, b2, b3);
}

// ---------------------------------------------------------------------------
// K5: scalar epilogue, 2 THREADS PER NODE (16 output channels each).
//   h2 = relu(agg2); h3 = relu(h2@fc1_w.T + fc1_b); out = h3.fc2_w + fc2_b
// 256 threads = 128 nodes/block, 782 blocks -> 6250 warps (2x residency vs
// thread-per-node). Per-thread: 8 LDS.128 (h) + 16x8 LDS.128 (w, 2-address
// broadcast = same wavefront total as 1t/node) + 1 shfl_xor combine.
// ---------------------------------------------------------------------------
#define K5_NODES 128
__global__ void k5_final(const float* __restrict__ fc1_w,
                         const float* __restrict__ fc1_b,
                         const float* __restrict__ fc2_w,
                         const float* __restrict__ fc2_b,
                         float* __restrict__ out) {
    __shared__ float sW[HID * HID];        // fc1_w, row-major (as-is)
    __shared__ float sb[HID];
    __shared__ float sf2[HID];
    __shared__ float sH[K5_NODES * 36];    // padded h2 rows
    int tid = threadIdx.x;
    for (int k = tid; k < HID * HID; k += 256) sW[k] = fc1_w[k];   // coalesced
    if (tid < HID) { sb[tid] = fc1_b[tid]; sf2[tid] = fc2_w[tid]; }

    int base = blockIdx.x * K5_NODES;
    for (int k = tid; k < K5_NODES * HID; k += 256) {
        int nl = k >> 5, i = k & 31;
        int n = base + nl;
        float v = 0.0f;
        if (n < N_NODES) v = fmaxf(g_agg2[n * HID + i], 0.0f);     // coalesced
        sH[nl * 36 + i] = v;                                        // conflict-free
    }
    __syncthreads();

    int nl = tid >> 1, half = tid & 1;
    float4 h4[8];
    const float4* hp = reinterpret_cast<const float4*>(&sH[nl * 36]);
#pragma unroll
    for (int i = 0; i < 8; i++) h4[i] = hp[i];

    const float4* w4 = reinterpret_cast<const float4*>(sW);
    float total = 0.0f;
#pragma unroll 4
    for (int j = 0; j < 16; j++) {
        int o = half * 16 + j;
        float a0 = sb[o], a1 = 0.0f, a2 = 0.0f, a3 = 0.0f;
#pragma unroll
        for (int i = 0; i < 8; i++) {
            float4 w = w4[o * 8 + i];   // 2-address broadcast LDS.128
            a0 = fmaf(h4[i].x, w.x, a0);
            a1 = fmaf(h4[i].y, w.y, a1);
            a2 = fmaf(h4[i].z, w.z, a2);
            a3 = fmaf(h4[i].w, w.w, a3);
        }
        float acc = (a0 + a1) + (a2 + a3);
        total = fmaf(fmaxf(acc, 0.0f), sf2[o], total);
    }
    total += __shfl_xor_sync(0xFFFFFFFFu, total, 1);
    int n = base + nl;
    if (half == 0 && n < N_NODES) out[n] = total + fc2_b[0];
}

// ---------------------------------------------------------------------------
extern "C" void kernel_launch(void* const* d_in, const int* in_sizes, int n_in,
                              void* d_out, int out_size) {
    const float* x       = (const float*)d_in[0];
    const int*   ei      = (const int*)  d_in[1];
    const float* ea      = (const float*)d_in[2];
    const float* nn1_w   = (const float*)d_in[3];
    const float* nn1_b   = (const float*)d_in[4];
    const float* root1   = (const float*)d_in[5];
    const float* bias1   = (const float*)d_in[6];
    const float* nn2_w   = (const float*)d_in[7];
    const float* nn2_b   = (const float*)d_in[8];
    const float* root2   = (const float*)d_in[9];
    const float* bias2   = (const float*)d_in[10];
    const float* fc1_w   = (const float*)d_in[11];
    const float* fc1_b   = (const float*)d_in[12];
    const float* fc2_w   = (const float*)d_in[13];
    const float* fc2_b   = (const float*)d_in[14];
    float* out = (float*)d_out;

    const int tpb = 256;
    int gridEdge = (N_EDGES * 4 + tpb - 1) / tpb;         // 4688
    int gridK3   = (N_NODES + 127) / 128;                 // 782
    int gridK5   = (N_NODES + K5_NODES - 1) / K5_NODES;   // 782

    void* agg1_ptr = nullptr;
    cudaGetSymbolAddress(&agg1_ptr, g_agg1);
    cudaMemsetAsync(agg1_ptr, 0, sizeof(float) * N_NODES * HID, 0);

    k2_edges1<<<gridEdge, tpb>>>(ei, ea, nn1_w, nn1_b, x);
    k3_node2<<<gridK3, tpb>>>(x, root1, bias1, nn2_w, nn2_b, root2, bias2);
    k4_edges2<<<gridEdge, tpb>>>(ei, ea);
    k5_final<<<gridK5, tpb>>>(fc1_w, fc1_b, fc2_w, fc2_b, out);
}

// round 11
// speedup vs baseline: 1.0769x; 1.0028x over previous
#include <cuda_runtime.h>
#include <cstdint>

#define N_NODES 100000
#define N_EDGES 300000
#define HID 32

// Scratch (device globals; no allocation allowed). 16B-aligned for v4 access.
__device__ __align__(16) float g_agg1[N_NODES * HID];  // layer1 edge-sum accumulator (memset 0)
// Interleaved per-node row (96 floats): 8 q-groups x [u4 | v4 | w4] (12 floats each)
__device__ __align__(16) float g_uvw[N_NODES * 96];
__device__ __align__(16) float g_agg2[N_NODES * HID];  // layer2 accumulator

__device__ __forceinline__ void red_add_v4(float* addr, float a, float b, float c, float d) {
    asm volatile("red.global.add.v4.f32 [%0], {%1,%2,%3,%4};"
                 :: "l"(addr), "f"(a), "f"(b), "f"(c), "f"(d) : "memory");
}

__device__ __forceinline__ uint32_t to_tf32(float f) {
    uint32_t r; asm("cvt.rna.tf32.f32 %0, %1;" : "=r"(r) : "f"(f)); return r;
}

__device__ __forceinline__ void mma_tf32_16n8k8(float c[4],
                                                uint32_t a0, uint32_t a1, uint32_t a2, uint32_t a3,
                                                uint32_t b0, uint32_t b1) {
    asm volatile(
        "mma.sync.aligned.m16n8k8.row.col.f32.tf32.tf32.f32 "
        "{%0,%1,%2,%3}, {%4,%5,%6,%7}, {%8,%9}, {%0,%1,%2,%3};"
        : "+f"(c[0]), "+f"(c[1]), "+f"(c[2]), "+f"(c[3])
        : "r"(a0), "r"(a1), "r"(a2), "r"(a3), "r"(b0), "r"(b1));
}

// ---------------------------------------------------------------------------
// K2: layer-1 edge messages. 2 edges per thread (even/odd pair), 4 channels.
// ---------------------------------------------------------------------------
__global__ void k2_edges1(const int* __restrict__ ei,
                          const float* __restrict__ ea,
                          const float* __restrict__ nn1_w,
                          const float* __restrict__ nn1_b,
                          const float* __restrict__ x) {
    int t = blockIdx.x * blockDim.x + threadIdx.x;
    if (t >= N_EDGES * 4) return;
    int e = (t >> 3) * 2;
    int q = (t & 7) * 4;
    int2   ss  = *reinterpret_cast<const int2*>(&ei[e]);
    int2   dd  = *reinterpret_cast<const int2*>(&ei[N_EDGES + e]);
    float4 eav = *reinterpret_cast<const float4*>(&ea[2 * e]);
    float2 xa  = *reinterpret_cast<const float2*>(&x[ss.x * 2]);
    float2 xb  = *reinterpret_cast<const float2*>(&x[ss.y * 2]);

    float m0[4], m1[4];
#pragma unroll
    for (int c = 0; c < 4; c++) {
        int ch = q + c, ch2 = ch + HID;
        float wA0 = nn1_w[2 * ch + 0],  wA1 = nn1_w[2 * ch + 1],  bA = nn1_b[ch];
        float wB0 = nn1_w[2 * ch2 + 0], wB1 = nn1_w[2 * ch2 + 1], bB = nn1_b[ch2];
        float w0a = fmaf(wA0, eav.x, fmaf(wA1, eav.y, bA));
        float w1a = fmaf(wB0, eav.x, fmaf(wB1, eav.y, bB));
        m0[c] = fmaf(xa.x, w0a, xa.y * w1a);
        float w0b = fmaf(wA0, eav.z, fmaf(wA1, eav.w, bA));
        float w1b = fmaf(wB0, eav.z, fmaf(wB1, eav.w, bB));
        m1[c] = fmaf(xb.x, w0b, xb.y * w1b);
    }
    red_add_v4(&g_agg1[dd.x * HID + q], m0[0], m0[1], m0[2], m0[3]);
    red_add_v4(&g_agg1[dd.y * HID + q], m1[0], m1[1], m1[2], m1[3]);
}

// ---------------------------------------------------------------------------
// K3: tensor-core (tf32 mma.sync) per-node precompute for layer 2 (R8 form,
// with INTERLEAVED uvw store: offset = (o/4)*12 + section*4 + (o%4)).
//   H[128x32] = relu(agg1 + x@root1 + bias1); Wcat[32x128] = [A | B | C | root2]
// ---------------------------------------------------------------------------
__global__ void k3_node2(const float* __restrict__ x,
                         const float* __restrict__ root1,
                         const float* __restrict__ bias1,
                         const float* __restrict__ nn2_w,
                         const float* __restrict__ nn2_b,
                         const float* __restrict__ root2,
                         const float* __restrict__ bias2) {
    __shared__ uint32_t sH[128 * 36];   // tf32 H: sH[m*36 + k]
    __shared__ uint32_t sW[32 * 136];   // tf32 Wcat: sW[k*136 + chan]
    __shared__ float sB2[32], sR1[64], sB1[32];
    int tid = threadIdx.x;
    if (tid < 64) sR1[tid] = root1[tid];
    if (tid < 32) { sB1[tid] = bias1[tid]; sB2[tid] = bias2[tid]; }
    __syncthreads();

    for (int idx = tid; idx < 32 * 128; idx += 256) {
        int k = idx >> 7, c = idx & 127;
        float w;
        if (c < 32)       w = nn2_w[(k * 32 + c) * 2 + 0];
        else if (c < 64)  w = nn2_w[(k * 32 + c - 32) * 2 + 1];
        else if (c < 96)  w = nn2_b[k * 32 + c - 64];
        else              w = root2[k * 32 + c - 96];
        sW[k * 136 + c] = to_tf32(w);
    }

    int blockBase = blockIdx.x * 128;
    for (int idx = tid; idx < 128 * 32; idx += 256) {
        int m = idx >> 5, kk = idx & 31;
        int n = blockBase + m;
        float val = 0.0f;
        if (n < N_NODES) {
            float2 xv = *reinterpret_cast<const float2*>(&x[n * 2]);
            float root = fmaf(xv.x, sR1[kk], fmaf(xv.y, sR1[HID + kk], sB1[kk]));
            val = fmaxf(g_agg1[n * HID + kk] + root, 0.0f);
        }
        sH[m * 36 + kk] = to_tf32(val);
    }
    __syncthreads();

    int warp = tid >> 5, lane = tid & 31;
    int gid = lane >> 2, tig = lane & 3;
    int mloc = warp * 16;

    uint32_t a[4][4];
#pragma unroll
    for (int kc = 0; kc < 4; kc++) {
        int k0 = kc * 8 + tig;
        a[kc][0] = sH[(mloc + gid) * 36 + k0];
        a[kc][1] = sH[(mloc + gid + 8) * 36 + k0];
        a[kc][2] = sH[(mloc + gid) * 36 + k0 + 4];
        a[kc][3] = sH[(mloc + gid + 8) * 36 + k0 + 4];
    }

    int node0 = blockBase + mloc + gid;
    int node1 = node0 + 8;
#pragma unroll
    for (int nt = 0; nt < 16; nt++) {
        float c[4] = {0.0f, 0.0f, 0.0f, 0.0f};
#pragma unroll
        for (int kc = 0; kc < 4; kc++) {
            uint32_t b0 = sW[(kc * 8 + tig) * 136 + nt * 8 + gid];
            uint32_t b1 = sW[(kc * 8 + tig + 4) * 136 + nt * 8 + gid];
            mma_tf32_16n8k8(c, a[kc][0], a[kc][1], a[kc][2], a[kc][3], b0, b1);
        }
        int chan = nt * 8 + tig * 2;
        if (nt < 12) {
            // Interleaved store: section = chan/32 (u/v/w), o = chan%32
            int section = chan >> 5, o = chan & 31;
            int off = (o >> 2) * 12 + section * 4 + (o & 3);   // pair stays contiguous
            if (node0 < N_NODES)
                *reinterpret_cast<float2*>(&g_uvw[node0 * 96 + off]) = make_float2(c[0], c[1]);
            if (node1 < N_NODES)
                *reinterpret_cast<float2*>(&g_uvw[node1 * 96 + off]) = make_float2(c[2], c[3]);
        } else {
            int cb = chan - 96;
            float b0f = sB2[cb], b1f = sB2[cb + 1];
            if (node0 < N_NODES)
                *reinterpret_cast<float2*>(&g_agg2[node0 * HID + cb]) = make_float2(c[0] + b0f, c[1] + b1f);
            if (node1 < N_NODES)
                *reinterpret_cast<float2*>(&g_agg2[node1 * HID + cb]) = make_float2(c[2] + b0f, c[3] + b1f);
        }
    }
}

// ---------------------------------------------------------------------------
// K4: layer-2 edge messages. 2 edges per thread, 4 channels (float4) each.
// INTERLEAVED gather: one 48B contiguous [u4|v4|w4] block per (edge, q-group)
// instead of 3 separate 128B lines -> ~2x fewer L2 sectors per thread.
// ---------------------------------------------------------------------------
__global__ void k4_edges2(const int* __restrict__ ei,
                          const float* __restrict__ ea) {
    int t = blockIdx.x * blockDim.x + threadIdx.x;
    if (t >= N_EDGES * 4) return;
    int e = (t >> 3) * 2;
    int q = (t & 7) * 4;                  // channel base
    int qd = (t & 7) * 12;                // interleaved block base
    int2   ss  = *reinterpret_cast<const int2*>(&ei[e]);
    int2   dd  = *reinterpret_cast<const int2*>(&ei[N_EDGES + e]);
    float4 eav = *reinterpret_cast<const float4*>(&ea[2 * e]);

    const float* ba = g_uvw + ss.x * 96 + qd;
    const float* bb = g_uvw + ss.y * 96 + qd;
    float4 u0 = *reinterpret_cast<const float4*>(ba);
    float4 v0 = *reinterpret_cast<const float4*>(ba + 4);
    float4 w0 = *reinterpret_cast<const float4*>(ba + 8);
    float4 u1 = *reinterpret_cast<const float4*>(bb);
    float4 v1 = *reinterpret_cast<const float4*>(bb + 4);
    float4 w1 = *reinterpret_cast<const float4*>(bb + 8);

    float a0 = fmaf(eav.x, u0.x, fmaf(eav.y, v0.x, w0.x));
    float a1 = fmaf(eav.x, u0.y, fmaf(eav.y, v0.y, w0.y));
    float a2 = fmaf(eav.x, u0.z, fmaf(eav.y, v0.z, w0.z));
    float a3 = fmaf(eav.x, u0.w, fmaf(eav.y, v0.w, w0.w));
    red_add_v4(&g_agg2[dd.x * HID + q], a0, a1, a2, a3);

    float b0 = fmaf(eav.z, u1.x, fmaf(eav.w, v1.x, w1.x));
    float b1 = fmaf(eav.z, u1.y, fmaf(eav.w, v1.y, w1.y));
    float b2 = fmaf(eav.z, u1.z, fmaf(eav.w, v1.z, w1.z));
    float b3 = fmaf(eav.z, u1.w, fmaf(eav.w, v1.w, w1.w));
    red_add_v4(&g_agg2[dd.y * HID + q], b0, b1, b2, b3);
}

// ---------------------------------------------------------------------------
// K5: epilogue, thread-per-node (PROVEN R5/R8 config: 256 nodes / 256 threads,
// single-address broadcast weight LDS -> 1 wavefront per load).
// ---------------------------------------------------------------------------
#define K5_NODES 256
__global__ void k5_final(const float* __restrict__ fc1_w,
                         const float* __restrict__ fc1_b,
                         const float* __restrict__ fc2_w,
                         const float* __restrict__ fc2_b,
                         float* __restrict__ out) {
    __shared__ float sW[HID * HID];        // fc1_w, row-major (as-is)
    __shared__ float sb[HID];
    __shared__ float sf2[HID];
    __shared__ float sH[K5_NODES * 36];    // padded h2 rows
    int tid = threadIdx.x;
    for (int k = tid; k < HID * HID; k += 256) sW[k] = fc1_w[k];   // coalesced
    if (tid < HID) { sb[tid] = fc1_b[tid]; sf2[tid] = fc2_w[tid]; }

    int base = blockIdx.x * K5_NODES;
    for (int k = tid; k < K5_NODES * HID; k += 256) {
        int nl = k >> 5, i = k & 31;
        int n = base + nl;
        float v = 0.0f;
        if (n < N_NODES) v = fmaxf(g_agg2[n * HID + i], 0.0f);     // coalesced
        sH[nl * 36 + i] = v;                                        // conflict-free
    }
    __syncthreads();

    float4 h4[8];
    const float4* hp = reinterpret_cast<const float4*>(&sH[tid * 36]);
#pragma unroll
    for (int i = 0; i < 8; i++) h4[i] = hp[i];

    const float4* w4 = reinterpret_cast<const float4*>(sW);
    float total = 0.0f;
#pragma unroll 4
    for (int o = 0; o < HID; o++) {
        float a0 = sb[o], a1 = 0.0f, a2 = 0.0f, a3 = 0.0f;
#pragma unroll
        for (int i = 0; i < 8; i++) {
            float4 w = w4[o * 8 + i];   // broadcast LDS.128 (1 wavefront)
            a0 = fmaf(h4[i].x, w.x, a0);
            a1 = fmaf(h4[i].y, w.y, a1);
            a2 = fmaf(h4[i].z, w.z, a2);
            a3 = fmaf(h4[i].w, w.w, a3);
        }
        float acc = (a0 + a1) + (a2 + a3);
        total = fmaf(fmaxf(acc, 0.0f), sf2[o], total);
    }
    int n = base + tid;
    if (n < N_NODES) out[n] = total + fc2_b[0];
}

// ---------------------------------------------------------------------------
extern "C" void kernel_launch(void* const* d_in, const int* in_sizes, int n_in,
                              void* d_out, int out_size) {
    const float* x       = (const float*)d_in[0];
    const int*   ei      = (const int*)  d_in[1];
    const float* ea      = (const float*)d_in[2];
    const float* nn1_w   = (const float*)d_in[3];
    const float* nn1_b   = (const float*)d_in[4];
    const float* root1   = (const float*)d_in[5];
    const float* bias1   = (const float*)d_in[6];
    const float* nn2_w   = (const float*)d_in[7];
    const float* nn2_b   = (const float*)d_in[8];
    const float* root2   = (const float*)d_in[9];
    const float* bias2   = (const float*)d_in[10];
    const float* fc1_w   = (const float*)d_in[11];
    const float* fc1_b   = (const float*)d_in[12];
    const float* fc2_w   = (const float*)d_in[13];
    const float* fc2_b   = (const float*)d_in[14];
    float* out = (float*)d_out;

    const int tpb = 256;
    int gridEdge = (N_EDGES * 4 + tpb - 1) / tpb;         // 4688
    int gridK3   = (N_NODES + 127) / 128;                 // 782
    int gridK5   = (N_NODES + K5_NODES - 1) / K5_NODES;   // 391

    void* agg1_ptr = nullptr;
    cudaGetSymbolAddress(&agg1_ptr, g_agg1);
    cudaMemsetAsync(agg1_ptr, 0, sizeof(float) * N_NODES * HID, 0);

    k2_edges1<<<gridEdge, tpb>>>(ei, ea, nn1_w, nn1_b, x);
    k3_node2<<<gridK3, tpb>>>(x, root1, bias1, nn2_w, nn2_b, root2, bias2);
    k4_edges2<<<gridEdge, tpb>>>(ei, ea);
    k5_final<<<gridK5, tpb>>>(fc1_w, fc1_b, fc2_w, fc2_b, out);
}

// round 12
// speedup vs baseline: 1.2353x; 1.1471x over previous
#include <cuda_runtime.h>
#include <cstdint>

#define N_NODES 100000
#define N_EDGES 300000
#define HID 32

// Scratch (device globals; no allocation allowed). 16B-aligned for v4 access.
__device__ __align__(16) float g_agg1[N_NODES * HID];  // layer1 edge-sum accumulator (memset 0)
__device__ __align__(16) float g_uvw[N_NODES * 96];    // per-node rows: [u(32) | v(32) | w(32)]
__device__ __align__(16) float g_agg2[N_NODES * HID];  // layer2 accumulator

__device__ __forceinline__ void red_add_v4(float* addr, float a, float b, float c, float d) {
    asm volatile("red.global.add.v4.f32 [%0], {%1,%2,%3,%4};"
                 :: "l"(addr), "f"(a), "f"(b), "f"(c), "f"(d) : "memory");
}

__device__ __forceinline__ uint32_t to_tf32(float f) {
    uint32_t r; asm("cvt.rna.tf32.f32 %0, %1;" : "=r"(r) : "f"(f)); return r;
}

__device__ __forceinline__ void mma_tf32_16n8k8(float c[4],
                                                uint32_t a0, uint32_t a1, uint32_t a2, uint32_t a3,
                                                uint32_t b0, uint32_t b1) {
    asm volatile(
        "mma.sync.aligned.m16n8k8.row.col.f32.tf32.tf32.f32 "
        "{%0,%1,%2,%3}, {%4,%5,%6,%7}, {%8,%9}, {%0,%1,%2,%3};"
        : "+f"(c[0]), "+f"(c[1]), "+f"(c[2]), "+f"(c[3])
        : "r"(a0), "r"(a1), "r"(a2), "r"(a3), "r"(b0), "r"(b1));
}

// ---------------------------------------------------------------------------
// K2: layer-1 edge messages. 2 edges per thread (even/odd pair), 4 channels.
// ---------------------------------------------------------------------------
__global__ void k2_edges1(const int* __restrict__ ei,
                          const float* __restrict__ ea,
                          const float* __restrict__ nn1_w,
                          const float* __restrict__ nn1_b,
                          const float* __restrict__ x) {
    int t = blockIdx.x * blockDim.x + threadIdx.x;
    if (t >= N_EDGES * 4) return;
    int e = (t >> 3) * 2;
    int q = (t & 7) * 4;
    int2   ss  = *reinterpret_cast<const int2*>(&ei[e]);
    int2   dd  = *reinterpret_cast<const int2*>(&ei[N_EDGES + e]);
    float4 eav = *reinterpret_cast<const float4*>(&ea[2 * e]);
    float2 xa  = *reinterpret_cast<const float2*>(&x[ss.x * 2]);
    float2 xb  = *reinterpret_cast<const float2*>(&x[ss.y * 2]);

    float m0[4], m1[4];
#pragma unroll
    for (int c = 0; c < 4; c++) {
        int ch = q + c, ch2 = ch + HID;
        float wA0 = nn1_w[2 * ch + 0],  wA1 = nn1_w[2 * ch + 1],  bA = nn1_b[ch];
        float wB0 = nn1_w[2 * ch2 + 0], wB1 = nn1_w[2 * ch2 + 1], bB = nn1_b[ch2];
        float w0a = fmaf(wA0, eav.x, fmaf(wA1, eav.y, bA));
        float w1a = fmaf(wB0, eav.x, fmaf(wB1, eav.y, bB));
        m0[c] = fmaf(xa.x, w0a, xa.y * w1a);
        float w0b = fmaf(wA0, eav.z, fmaf(wA1, eav.w, bA));
        float w1b = fmaf(wB0, eav.z, fmaf(wB1, eav.w, bB));
        m1[c] = fmaf(xb.x, w0b, xb.y * w1b);
    }
    red_add_v4(&g_agg1[dd.x * HID + q], m0[0], m0[1], m0[2], m0[3]);
    red_add_v4(&g_agg1[dd.y * HID + q], m1[0], m1[1], m1[2], m1[3]);
}

// ---------------------------------------------------------------------------
// K3: tensor-core (tf32 mma.sync) per-node precompute for layer 2 (R8 form).
//   H[128x32] = relu(agg1 + x@root1 + bias1); Wcat[32x128] = [A | B | C | root2]
//   D = H @ Wcat -> chans 0-95 -> g_uvw ; chans 96-127 (+bias2) -> g_agg2
// ---------------------------------------------------------------------------
__global__ void k3_node2(const float* __restrict__ x,
                         const float* __restrict__ root1,
                         const float* __restrict__ bias1,
                         const float* __restrict__ nn2_w,
                         const float* __restrict__ nn2_b,
                         const float* __restrict__ root2,
                         const float* __restrict__ bias2) {
    __shared__ uint32_t sH[128 * 36];   // tf32 H: sH[m*36 + k]
    __shared__ uint32_t sW[32 * 136];   // tf32 Wcat: sW[k*136 + chan]
    __shared__ float sB2[32], sR1[64], sB1[32];
    int tid = threadIdx.x;
    if (tid < 64) sR1[tid] = root1[tid];
    if (tid < 32) { sB1[tid] = bias1[tid]; sB2[tid] = bias2[tid]; }
    __syncthreads();

    for (int idx = tid; idx < 32 * 128; idx += 256) {
        int k = idx >> 7, c = idx & 127;
        float w;
        if (c < 32)       w = nn2_w[(k * 32 + c) * 2 + 0];
        else if (c < 64)  w = nn2_w[(k * 32 + c - 32) * 2 + 1];
        else if (c < 96)  w = nn2_b[k * 32 + c - 64];
        else              w = root2[k * 32 + c - 96];
        sW[k * 136 + c] = to_tf32(w);
    }

    int blockBase = blockIdx.x * 128;
    for (int idx = tid; idx < 128 * 32; idx += 256) {
        int m = idx >> 5, kk = idx & 31;
        int n = blockBase + m;
        float val = 0.0f;
        if (n < N_NODES) {
            float2 xv = *reinterpret_cast<const float2*>(&x[n * 2]);
            float root = fmaf(xv.x, sR1[kk], fmaf(xv.y, sR1[HID + kk], sB1[kk]));
            val = fmaxf(g_agg1[n * HID + kk] + root, 0.0f);
        }
        sH[m * 36 + kk] = to_tf32(val);
    }
    __syncthreads();

    int warp = tid >> 5, lane = tid & 31;
    int gid = lane >> 2, tig = lane & 3;
    int mloc = warp * 16;

    uint32_t a[4][4];
#pragma unroll
    for (int kc = 0; kc < 4; kc++) {
        int k0 = kc * 8 + tig;
        a[kc][0] = sH[(mloc + gid) * 36 + k0];
        a[kc][1] = sH[(mloc + gid + 8) * 36 + k0];
        a[kc][2] = sH[(mloc + gid) * 36 + k0 + 4];
        a[kc][3] = sH[(mloc + gid + 8) * 36 + k0 + 4];
    }

    int node0 = blockBase + mloc + gid;
    int node1 = node0 + 8;
#pragma unroll
    for (int nt = 0; nt < 16; nt++) {
        float c[4] = {0.0f, 0.0f, 0.0f, 0.0f};
#pragma unroll
        for (int kc = 0; kc < 4; kc++) {
            uint32_t b0 = sW[(kc * 8 + tig) * 136 + nt * 8 + gid];
            uint32_t b1 = sW[(kc * 8 + tig + 4) * 136 + nt * 8 + gid];
            mma_tf32_16n8k8(c, a[kc][0], a[kc][1], a[kc][2], a[kc][3], b0, b1);
        }
        int chan = nt * 8 + tig * 2;
        if (nt < 12) {
            if (node0 < N_NODES)
                *reinterpret_cast<float2*>(&g_uvw[node0 * 96 + chan]) = make_float2(c[0], c[1]);
            if (node1 < N_NODES)
                *reinterpret_cast<float2*>(&g_uvw[node1 * 96 + chan]) = make_float2(c[2], c[3]);
        } else {
            int cb = chan - 96;
            float b0f = sB2[cb], b1f = sB2[cb + 1];
            if (node0 < N_NODES)
                *reinterpret_cast<float2*>(&g_agg2[node0 * HID + cb]) = make_float2(c[0] + b0f, c[1] + b1f);
            if (node1 < N_NODES)
                *reinterpret_cast<float2*>(&g_agg2[node1 * HID + cb]) = make_float2(c[2] + b0f, c[3] + b1f);
        }
    }
}

// ---------------------------------------------------------------------------
// K4: layer-2 edge messages. 2 edges per thread, 4 channels (float4) each.
// Planar uvw layout (R8): each load instruction is a single-line coalesced
// wavefront across the 8 same-edge threads.
// ---------------------------------------------------------------------------
__global__ void k4_edges2(const int* __restrict__ ei,
                          const float* __restrict__ ea) {
    int t = blockIdx.x * blockDim.x + threadIdx.x;
    if (t >= N_EDGES * 4) return;
    int e = (t >> 3) * 2;
    int q = (t & 7) * 4;
    int2   ss  = *reinterpret_cast<const int2*>(&ei[e]);
    int2   dd  = *reinterpret_cast<const int2*>(&ei[N_EDGES + e]);
    float4 eav = *reinterpret_cast<const float4*>(&ea[2 * e]);

    const float* ba = g_uvw + ss.x * 96;
    const float* bb = g_uvw + ss.y * 96;
    float4 u0 = *reinterpret_cast<const float4*>(ba + q);
    float4 v0 = *reinterpret_cast<const float4*>(ba + 32 + q);
    float4 w0 = *reinterpret_cast<const float4*>(ba + 64 + q);
    float4 u1 = *reinterpret_cast<const float4*>(bb + q);
    float4 v1 = *reinterpret_cast<const float4*>(bb + 32 + q);
    float4 w1 = *reinterpret_cast<const float4*>(bb + 64 + q);

    float a0 = fmaf(eav.x, u0.x, fmaf(eav.y, v0.x, w0.x));
    float a1 = fmaf(eav.x, u0.y, fmaf(eav.y, v0.y, w0.y));
    float a2 = fmaf(eav.x, u0.z, fmaf(eav.y, v0.z, w0.z));
    float a3 = fmaf(eav.x, u0.w, fmaf(eav.y, v0.w, w0.w));
    red_add_v4(&g_agg2[dd.x * HID + q], a0, a1, a2, a3);

    float b0 = fmaf(eav.z, u1.x, fmaf(eav.w, v1.x, w1.x));
    float b1 = fmaf(eav.z, u1.y, fmaf(eav.w, v1.y, w1.y));
    float b2 = fmaf(eav.z, u1.z, fmaf(eav.w, v1.z, w1.z));
    float b3 = fmaf(eav.z, u1.w, fmaf(eav.w, v1.w, w1.w));
    red_add_v4(&g_agg2[dd.y * HID + q], b0, b1, b2, b3);
}

// ---------------------------------------------------------------------------
// K5: epilogue, 2 NODES PER THREAD (same warp shape as R8, double ILP).
// 128 threads/block handle 256 nodes: node A = base+tid, node B = base+128+tid.
// Weight LDS.128 stays single-address broadcast (1 wavefront) but feeds 8
// independent FMA chains; weight-load cost per node halves.
// ---------------------------------------------------------------------------
#define K5_THREADS 128
#define K5_NODES 256
__global__ void __launch_bounds__(K5_THREADS)
k5_final(const float* __restrict__ fc1_w,
         const float* __restrict__ fc1_b,
         const float* __restrict__ fc2_w,
         const float* __restrict__ fc2_b,
         float* __restrict__ out) {
    __shared__ float sW[HID * HID];        // fc1_w, row-major (as-is)
    __shared__ float sb[HID];
    __shared__ float sf2[HID];
    __shared__ float sH[K5_NODES * 36];    // padded h2 rows
    int tid = threadIdx.x;
    for (int k = tid; k < HID * HID; k += K5_THREADS) sW[k] = fc1_w[k];   // coalesced
    if (tid < HID) { sb[tid] = fc1_b[tid]; sf2[tid] = fc2_w[tid]; }

    int base = blockIdx.x * K5_NODES;
    for (int k = tid; k < K5_NODES * HID; k += K5_THREADS) {
        int nl = k >> 5, i = k & 31;
        int n = base + nl;
        float v = 0.0f;
        if (n < N_NODES) v = fmaxf(g_agg2[n * HID + i], 0.0f);     // coalesced
        sH[nl * 36 + i] = v;                                        // conflict-free
    }
    __syncthreads();

    float4 hA[8], hB[8];
    const float4* hpA = reinterpret_cast<const float4*>(&sH[tid * 36]);
    const float4* hpB = reinterpret_cast<const float4*>(&sH[(tid + 128) * 36]);
#pragma unroll
    for (int i = 0; i < 8; i++) { hA[i] = hpA[i]; hB[i] = hpB[i]; }

    const float4* w4 = reinterpret_cast<const float4*>(sW);
    float tA = 0.0f, tB = 0.0f;
#pragma unroll 4
    for (int o = 0; o < HID; o++) {
        float a0 = sb[o], a1 = 0.0f, a2 = 0.0f, a3 = 0.0f;
        float b0 = sb[o], b1 = 0.0f, b2 = 0.0f, b3 = 0.0f;
#pragma unroll
        for (int i = 0; i < 8; i++) {
            float4 w = w4[o * 8 + i];   // broadcast LDS.128 (1 wavefront), feeds 8 chains
            a0 = fmaf(hA[i].x, w.x, a0);
            a1 = fmaf(hA[i].y, w.y, a1);
            a2 = fmaf(hA[i].z, w.z, a2);
            a3 = fmaf(hA[i].w, w.w, a3);
            b0 = fmaf(hB[i].x, w.x, b0);
            b1 = fmaf(hB[i].y, w.y, b1);
            b2 = fmaf(hB[i].z, w.z, b2);
            b3 = fmaf(hB[i].w, w.w, b3);
        }
        float f2 = sf2[o];
        tA = fmaf(fmaxf((a0 + a1) + (a2 + a3), 0.0f), f2, tA);
        tB = fmaf(fmaxf((b0 + b1) + (b2 + b3), 0.0f), f2, tB);
    }
    float bias = fc2_b[0];
    int nA = base + tid, nB = base + 128 + tid;
    if (nA < N_NODES) out[nA] = tA + bias;
    if (nB < N_NODES) out[nB] = tB + bias;
}

// ---------------------------------------------------------------------------
extern "C" void kernel_launch(void* const* d_in, const int* in_sizes, int n_in,
                              void* d_out, int out_size) {
    const float* x       = (const float*)d_in[0];
    const int*   ei      = (const int*)  d_in[1];
    const float* ea      = (const float*)d_in[2];
    const float* nn1_w   = (const float*)d_in[3];
    const float* nn1_b   = (const float*)d_in[4];
    const float* root1   = (const float*)d_in[5];
    const float* bias1   = (const float*)d_in[6];
    const float* nn2_w   = (const float*)d_in[7];
    const float* nn2_b   = (const float*)d_in[8];
    const float* root2   = (const float*)d_in[9];
    const float* bias2   = (const float*)d_in[10];
    const float* fc1_w   = (const float*)d_in[11];
    const float* fc1_b   = (const float*)d_in[12];
    const float* fc2_w   = (const float*)d_in[13];
    const float* fc2_b   = (const float*)d_in[14];
    float* out = (float*)d_out;

    const int tpb = 256;
    int gridEdge = (N_EDGES * 4 + tpb - 1) / tpb;         // 4688
    int gridK3   = (N_NODES + 127) / 128;                 // 782
    int gridK5   = (N_NODES + K5_NODES - 1) / K5_NODES;   // 391

    void* agg1_ptr = nullptr;
    cudaGetSymbolAddress(&agg1_ptr, g_agg1);
    cudaMemsetAsync(agg1_ptr, 0, sizeof(float) * N_NODES * HID, 0);

    k2_edges1<<<gridEdge, tpb>>>(ei, ea, nn1_w, nn1_b, x);
    k3_node2<<<gridK3, tpb>>>(x, root1, bias1, nn2_w, nn2_b, root2, bias2);
    k4_edges2<<<gridEdge, tpb>>>(ei, ea);
    k5_final<<<gridK5, K5_THREADS>>>(fc1_w, fc1_b, fc2_w, fc2_b, out);
}